// round 1
// baseline (speedup 1.0000x reference)
#include <cuda_runtime.h>
#include <math.h>

#define N_TOK  32768
#define HID    1024
#define NEXP   64
#define H4     256

// GEMM tiling
#define BM 256
#define BN 64
#define BK 8
#define TM 8
#define TN 4
#define GTHREADS 512   // (BM/TM)*(BN/TN) = 32*16

// ---------------- scratch (no allocations allowed) ----------------
__device__ float g_u[N_TOK];      // h @ w2^T + b2 per token
__device__ float g_load[NEXP];    // sum over tokens of probs
__device__ float g_ent;           // sum over tokens of per-token entropy

// ---------------- init ----------------
__global__ void init_kernel(const float* __restrict__ b2) {
    int i = blockIdx.x * blockDim.x + threadIdx.x;
    if (i < N_TOK) g_u[i] = b2[0];
    if (i < NEXP)  g_load[i] = 0.0f;
    if (i == 0)    g_ent = 0.0f;
}

// ---------------- fused GEMM: router logits + MLP hidden + u partials ----------------
// grid = (5, N_TOK/BM). blockIdx.x==0 -> router_w (write logits),
// blockIdx.x in 1..4 -> w1 rows [(ft-1)*64, ft*64): relu + dot w2 slice -> atomicAdd u.
__global__ __launch_bounds__(GTHREADS, 1)
void gemm_kernel(const float* __restrict__ X,
                 const float* __restrict__ RW,
                 const float* __restrict__ W1,
                 const float* __restrict__ B1,
                 const float* __restrict__ W2,
                 float* __restrict__ logits)
{
    __shared__ float sA[BK][BM];   // 8 KB
    __shared__ float sB[BK][BN];   // 2 KB

    const int ft = blockIdx.x;
    const int m0 = blockIdx.y * BM;
    const float* Bmat = (ft == 0) ? RW : (W1 + (size_t)(ft - 1) * BN * HID);

    const int tid = threadIdx.x;
    const int ty = tid >> 4;       // 0..31 -> m sub-tile
    const int tx = tid & 15;       // 0..15 -> n sub-tile

    float acc[TM][TN];
#pragma unroll
    for (int i = 0; i < TM; i++)
#pragma unroll
        for (int j = 0; j < TN; j++) acc[i][j] = 0.0f;

    // loader roles:
    //  threads [0,256): A row m = tid, 8 floats (2 x float4) per chunk
    //  threads [256,384): B, t2 = tid-256, f = t2&63, kq = t2>>6 (0..1), one float4
    float4 pa0 = make_float4(0,0,0,0), pa1 = make_float4(0,0,0,0);
    float4 pb  = make_float4(0,0,0,0);

    const float* arow = X + (size_t)(m0 + tid) * HID;     // valid for tid<256
    int t2 = tid - 256;
    int bf = t2 & 63;
    int bkq = (t2 >> 6) & 1;
    const float* brow = Bmat + (size_t)bf * HID + bkq * 4;

    // prefetch chunk 0
    if (tid < 256) {
        pa0 = *reinterpret_cast<const float4*>(arow + 0);
        pa1 = *reinterpret_cast<const float4*>(arow + 4);
    } else if (tid < 384) {
        pb = *reinterpret_cast<const float4*>(brow + 0);
    }

    for (int kc = 0; kc < HID; kc += BK) {
        __syncthreads();   // previous chunk's compute done
        if (tid < 256) {
            sA[0][tid] = pa0.x; sA[1][tid] = pa0.y; sA[2][tid] = pa0.z; sA[3][tid] = pa0.w;
            sA[4][tid] = pa1.x; sA[5][tid] = pa1.y; sA[6][tid] = pa1.z; sA[7][tid] = pa1.w;
        } else if (tid < 384) {
            int kb = bkq * 4;
            sB[kb + 0][bf] = pb.x; sB[kb + 1][bf] = pb.y;
            sB[kb + 2][bf] = pb.z; sB[kb + 3][bf] = pb.w;
        }
        __syncthreads();   // smem visible

        int kn = kc + BK;
        if (kn < HID) {
            if (tid < 256) {
                pa0 = *reinterpret_cast<const float4*>(arow + kn + 0);
                pa1 = *reinterpret_cast<const float4*>(arow + kn + 4);
            } else if (tid < 384) {
                pb = *reinterpret_cast<const float4*>(brow + kn);
            }
        }

        // fresh accumulator per chunk (two-level accumulation: lower rounding drift)
        float cacc[TM][TN];
#pragma unroll
        for (int i = 0; i < TM; i++)
#pragma unroll
            for (int j = 0; j < TN; j++) cacc[i][j] = 0.0f;

#pragma unroll
        for (int kk = 0; kk < BK; kk++) {
            float a[TM], b[TN];
            *reinterpret_cast<float4*>(&a[0]) = *reinterpret_cast<const float4*>(&sA[kk][ty * TM + 0]);
            *reinterpret_cast<float4*>(&a[4]) = *reinterpret_cast<const float4*>(&sA[kk][ty * TM + 4]);
            *reinterpret_cast<float4*>(&b[0]) = *reinterpret_cast<const float4*>(&sB[kk][tx * TN]);
#pragma unroll
            for (int i = 0; i < TM; i++)
#pragma unroll
                for (int j = 0; j < TN; j++)
                    cacc[i][j] = fmaf(a[i], b[j], cacc[i][j]);
        }
#pragma unroll
        for (int i = 0; i < TM; i++)
#pragma unroll
            for (int j = 0; j < TN; j++) acc[i][j] += cacc[i][j];
    }

    if (ft == 0) {
        // write router logits [N, 64]
#pragma unroll
        for (int i = 0; i < TM; i++) {
            int m = m0 + ty * TM + i;
            float4 v = make_float4(acc[i][0], acc[i][1], acc[i][2], acc[i][3]);
            *reinterpret_cast<float4*>(logits + (size_t)m * NEXP + tx * TN) = v;
        }
    } else {
        // relu(acc + b1) dot w2-slice; reduce over tx (16 lanes = low 4 lane bits)
        int hbase = (ft - 1) * BN + tx * TN;
        float b1v[TN], w2v[TN];
#pragma unroll
        for (int j = 0; j < TN; j++) { b1v[j] = B1[hbase + j]; w2v[j] = W2[hbase + j]; }
#pragma unroll
        for (int i = 0; i < TM; i++) {
            float s = 0.0f;
#pragma unroll
            for (int j = 0; j < TN; j++) {
                float h = fmaxf(acc[i][j] + b1v[j], 0.0f);
                s = fmaf(h, w2v[j], s);
            }
            s += __shfl_xor_sync(0xffffffffu, s, 1);
            s += __shfl_xor_sync(0xffffffffu, s, 2);
            s += __shfl_xor_sync(0xffffffffu, s, 4);
            s += __shfl_xor_sync(0xffffffffu, s, 8);
            if (tx == 0) atomicAdd(&g_u[m0 + ty * TM + i], s);
        }
    }
}

// ---------------- per-token top-k / softmax / stats ----------------
#define CTOK 128
__global__ __launch_bounds__(CTOK)
void topk_kernel(const float* __restrict__ logits,
                 float* __restrict__ sel,
                 float* __restrict__ wts)
{
    __shared__ float sl[CTOK][NEXP + 1];   // padded: conflict-free row reads
    __shared__ float sload[NEXP];
    __shared__ float s_ent;

    const int tid = threadIdx.x;
    const int t0 = blockIdx.x * CTOK;

    if (tid < NEXP) sload[tid] = 0.0f;
    if (tid == 0) s_ent = 0.0f;

    // coalesced load of this block's logits
    const float* src = logits + (size_t)t0 * NEXP;
    for (int idx = tid; idx < CTOK * NEXP; idx += CTOK) {
        sl[idx >> 6][idx & 63] = src[idx];
    }
    __syncthreads();

    const int m = t0 + tid;

    // ordered top-4, stable (lower index wins ties via strict >)
    float v0 = -INFINITY, v1 = -INFINITY, v2 = -INFINITY, v3 = -INFINITY;
    int i0 = 0, i1 = 0, i2 = 0, i3 = 0;
#pragma unroll
    for (int j = 0; j < NEXP; j++) {
        float x = sl[tid][j];
        if (x > v3) {
            if (x > v0)      { v3=v2;i3=i2; v2=v1;i2=i1; v1=v0;i1=i0; v0=x;i0=j; }
            else if (x > v1) { v3=v2;i3=i2; v2=v1;i2=i1; v1=x;i1=j; }
            else if (x > v2) { v3=v2;i3=i2; v2=x;i2=j; }
            else             { v3=x;i3=j; }
        }
    }

    // full softmax: single exp pass, store exp in place
    float mx = v0;
    float se = 0.0f;
#pragma unroll
    for (int j = 0; j < NEXP; j++) {
        float e = __expf(sl[tid][j] - mx);
        se += e;
        sl[tid][j] = e;
    }
    float inv = 1.0f / se;

    // probs: entropy + expert-load accumulation (rotated index -> spread atomics)
    float ent = 0.0f;
#pragma unroll
    for (int jj = 0; jj < NEXP; jj++) {
        int e = (jj + tid) & 63;
        float p = sl[tid][e] * inv;
        ent -= p * __logf(p + 1e-8f);
        atomicAdd(&sload[e], p);
    }
    atomicAdd(&s_ent, ent);

    // adaptive k from complexity predictor
    float u = g_u[m];
    float cplx = 1.0f / (1.0f + expf(-u));
    int kk = (cplx > 0.5f) ? 4 : 1;

    // masked softmax over top-k
    float e0 = 1.0f;                                 // exp(v0 - v0)
    float e1 = (kk > 1) ? expf(v1 - v0) : 0.0f;
    float e2 = (kk > 2) ? expf(v2 - v0) : 0.0f;
    float e3 = (kk > 3) ? expf(v3 - v0) : 0.0f;
    float wsuminv = 1.0f / (e0 + e1 + e2 + e3);

    float* selp = sel + (size_t)m * 4;
    float* wtp  = wts + (size_t)m * 4;
    selp[0] = (float)i0;
    selp[1] = (float)((kk > 1) ? i1 : 0);
    selp[2] = (float)((kk > 2) ? i2 : 0);
    selp[3] = (float)((kk > 3) ? i3 : 0);
    wtp[0] = e0 * wsuminv;
    wtp[1] = e1 * wsuminv;
    wtp[2] = e2 * wsuminv;
    wtp[3] = e3 * wsuminv;

    __syncthreads();
    if (tid < NEXP) atomicAdd(&g_load[tid], sload[tid]);
    if (tid == 0)   atomicAdd(&g_ent, s_ent);
}

// ---------------- finalize scalars ----------------
__global__ void finalize_kernel(float* __restrict__ out_var, float* __restrict__ out_ent) {
    __shared__ float xs[NEXP];
    int tid = threadIdx.x;
    xs[tid] = g_load[tid] * (1.0f / N_TOK);
    __syncthreads();
    if (tid == 0) {
        float mean = 0.0f;
        for (int e = 0; e < NEXP; e++) mean += xs[e];
        mean *= (1.0f / NEXP);
        float var = 0.0f;
        for (int e = 0; e < NEXP; e++) {
            float d = xs[e] - mean;
            var += d * d;
        }
        var *= (1.0f / (NEXP - 1));   // ddof=1
        out_var[0] = var;
        out_ent[0] = g_ent * (1.0f / N_TOK);
    }
}

// ---------------- launch ----------------
extern "C" void kernel_launch(void* const* d_in, const int* in_sizes, int n_in,
                              void* d_out, int out_size) {
    const float* X  = (const float*)d_in[0];   // [32768, 1024]
    const float* RW = (const float*)d_in[1];   // [64, 1024]
    const float* W1 = (const float*)d_in[2];   // [256, 1024]
    const float* B1 = (const float*)d_in[3];   // [256]
    const float* W2 = (const float*)d_in[4];   // [1, 256]
    const float* B2 = (const float*)d_in[5];   // [1]

    float* out    = (float*)d_out;
    float* logits = out;                              // N*64
    float* sel    = logits + (size_t)N_TOK * NEXP;    // N*4
    float* wts    = sel + (size_t)N_TOK * 4;          // N*4
    float* ovar   = wts + (size_t)N_TOK * 4;          // 1
    float* oent   = ovar + 1;                         // 1

    init_kernel<<<N_TOK / 256, 256>>>(B2);
    gemm_kernel<<<dim3(5, N_TOK / BM), GTHREADS>>>(X, RW, W1, B1, W2, logits);
    topk_kernel<<<N_TOK / CTOK, CTOK>>>(logits, sel, wts);
    finalize_kernel<<<1, NEXP>>>(ovar, oent);
}

// round 3
// speedup vs baseline: 3.3472x; 3.3472x over previous
#include <cuda_runtime.h>
#include <cuda_fp16.h>
#include <stdint.h>
#include <math.h>

#define N_TOK  32768
#define HID    1024
#define NEXP   64
#define H4     256
#define N_TOT  320          // 64 router + 256 hidden

#define MT      128         // M rows per CTA
#define KC      64          // K per chunk
#define NCHUNK  (HID / KC)  // 16
#define THREADS 512

// smem stage layout (bytes)
#define A_HI   0
#define A_LO   16384
#define B_HI   32768
#define B_LO   73728
#define ST_BYTES 114688
#define SMEM_TOTAL (2 * ST_BYTES)   // 229376

// ---------------- device scratch ----------------
__device__ __align__(16) __half g_xhi[(size_t)N_TOK * HID];
__device__ __align__(16) __half g_xlo[(size_t)N_TOK * HID];
__device__ __align__(16) __half g_whi[N_TOT * HID];
__device__ __align__(16) __half g_wlo[N_TOT * HID];
__device__ float g_u[N_TOK];
__device__ float g_load[NEXP];
__device__ float g_ent;

__device__ __forceinline__ uint32_t swz(uint32_t o) { return o ^ ((o >> 3) & 0x70); }
__device__ __forceinline__ uint32_t smem_u32(const void* p) {
    uint32_t a;
    asm("{ .reg .u64 t; cvta.to.shared.u64 t, %1; cvt.u32.u64 %0, t; }" : "=r"(a) : "l"(p));
    return a;
}
__device__ __forceinline__ void cp16(uint32_t dst, const void* src) {
    asm volatile("cp.async.cg.shared.global [%0], [%1], 16;"
                 :: "r"(dst), "l"(__cvta_generic_to_global(src)));
}
__device__ __forceinline__ void ldsm4(uint32_t* r, uint32_t addr) {
    asm volatile("ldmatrix.sync.aligned.m8n8.x4.shared.b16 {%0,%1,%2,%3}, [%4];"
                 : "=r"(r[0]), "=r"(r[1]), "=r"(r[2]), "=r"(r[3]) : "r"(addr));
}
__device__ __forceinline__ void mma16816(float* c, const uint32_t* a, const uint32_t* b) {
    asm volatile(
        "mma.sync.aligned.m16n8k16.row.col.f32.f16.f16.f32 "
        "{%0,%1,%2,%3}, {%4,%5,%6,%7}, {%8,%9}, {%0,%1,%2,%3};"
        : "+f"(c[0]), "+f"(c[1]), "+f"(c[2]), "+f"(c[3])
        : "r"(a[0]), "r"(a[1]), "r"(a[2]), "r"(a[3]), "r"(b[0]), "r"(b[1]));
}

// ---------------- prep: fp32 -> fp16 hi/lo ----------------
__global__ void prep_w_kernel(const float* __restrict__ RW, const float* __restrict__ W1) {
    int i = blockIdx.x * blockDim.x + threadIdx.x;
    if (i >= N_TOT * HID) return;
    int row = i >> 10;
    float v = (row < NEXP) ? RW[i] : W1[i - NEXP * HID];
    __half h = __float2half_rn(v);
    g_whi[i] = h;
    g_wlo[i] = __float2half_rn(v - __half2float(h));
}

__global__ void prep_x_kernel(const float* __restrict__ X) {
    size_t u = (size_t)blockIdx.x * blockDim.x + threadIdx.x;   // 8-elem unit
    const float4* src = reinterpret_cast<const float4*>(X) + u * 2;
    float4 f0 = src[0], f1 = src[1];
    __half2 h0 = __floats2half2_rn(f0.x, f0.y);
    __half2 h1 = __floats2half2_rn(f0.z, f0.w);
    __half2 h2 = __floats2half2_rn(f1.x, f1.y);
    __half2 h3 = __floats2half2_rn(f1.z, f1.w);
    float2 g0 = __half22float2(h0), g1 = __half22float2(h1);
    float2 g2 = __half22float2(h2), g3 = __half22float2(h3);
    __half2 l0 = __floats2half2_rn(f0.x - g0.x, f0.y - g0.y);
    __half2 l1 = __floats2half2_rn(f0.z - g1.x, f0.w - g1.y);
    __half2 l2 = __floats2half2_rn(f1.x - g2.x, f1.y - g2.y);
    __half2 l3 = __floats2half2_rn(f1.z - g3.x, f1.w - g3.y);
    reinterpret_cast<__half2*>(g_xhi)[u * 4 + 0] = h0;
    reinterpret_cast<__half2*>(g_xhi)[u * 4 + 1] = h1;
    reinterpret_cast<__half2*>(g_xhi)[u * 4 + 2] = h2;
    reinterpret_cast<__half2*>(g_xhi)[u * 4 + 3] = h3;
    reinterpret_cast<__half2*>(g_xlo)[u * 4 + 0] = l0;
    reinterpret_cast<__half2*>(g_xlo)[u * 4 + 1] = l1;
    reinterpret_cast<__half2*>(g_xlo)[u * 4 + 2] = l2;
    reinterpret_cast<__half2*>(g_xlo)[u * 4 + 3] = l3;
}

__global__ void init_kernel(const float* __restrict__ b2) {
    int i = blockIdx.x * blockDim.x + threadIdx.x;
    if (i < N_TOK) g_u[i] = b2[0];
    if (i < NEXP)  g_load[i] = 0.0f;
    if (i == 0)    g_ent = 0.0f;
}

// ---------------- GEMM: X @ [RW ; W1]^T via fp16x3 mma.sync ----------------
__global__ void __launch_bounds__(THREADS, 1)
gemm_kernel(const float* __restrict__ B1, const float* __restrict__ W2,
            float* __restrict__ logits)
{
    extern __shared__ __align__(1024) char smem[];
    const uint32_t sbase = smem_u32(smem);
    const int tid = threadIdx.x;
    const int lane = tid & 31;
    const int wid = tid >> 5;
    const int wm = wid & 3;          // 4 m-warps * 32 rows
    const int wn = wid >> 2;         // 4 n-warps * 80 cols
    const int m0 = blockIdx.x * MT;

    float acc[2][10][4];
#pragma unroll
    for (int i = 0; i < 2; i++)
#pragma unroll
        for (int j = 0; j < 10; j++)
#pragma unroll
            for (int r = 0; r < 4; r++) acc[i][j][r] = 0.0f;

    // ldmatrix address precompute
    uint32_t aBase[2], aXor[2];
#pragma unroll
    for (int mt = 0; mt < 2; mt++) {
        int row = wm * 32 + mt * 16 + (lane & 15);
        aBase[mt] = (uint32_t)row * 128;
        aXor[mt] = ((uint32_t)row * 16) & 0x70;
    }
    const uint32_t aKB = ((lane >> 4) & 1) * 16;

    uint32_t bBase[5], bXor[5];
#pragma unroll
    for (int p = 0; p < 5; p++) {
        int row = wn * 80 + (p * 2 + ((lane >> 4) & 1)) * 8 + (lane & 7);
        bBase[p] = (uint32_t)row * 128;
        bXor[p] = ((uint32_t)row * 16) & 0x70;
    }
    const uint32_t bKB = ((lane >> 3) & 1) * 16;

    // chunk issuer (cp.async, 14 units of 16B per thread)
    auto issue = [&](int c) {
        const uint32_t sb = sbase + (c & 1) * ST_BYTES;
        const size_t k0 = (size_t)c * KC;
#pragma unroll
        for (int it = 0; it < 14; it++) {
            int u = tid + it * THREADS;
            const __half* src;
            uint32_t dst;
            if (u < 2048) {
                int v = u >> 10, j = u & 1023;
                int row = j >> 3, cq = j & 7;
                src = (v ? g_xlo : g_xhi) + (size_t)(m0 + row) * HID + k0 + cq * 8;
                dst = sb + (v ? A_LO : A_HI) + swz(row * 128 + cq * 16);
            } else {
                int t = u - 2048;
                int v = t >= 2560;
                int j = v ? t - 2560 : t;
                int row = j >> 3, cq = j & 7;
                src = (v ? g_wlo : g_whi) + (size_t)row * HID + k0 + cq * 8;
                dst = sb + (v ? B_LO : B_HI) + swz(row * 128 + cq * 16);
            }
            cp16(dst, src);
        }
        asm volatile("cp.async.commit_group;");
    };

    issue(0);

    for (int c = 0; c < NCHUNK; c++) {
        if (c + 1 < NCHUNK) {
            issue(c + 1);
            asm volatile("cp.async.wait_group 1;");
        } else {
            asm volatile("cp.async.wait_group 0;");
        }
        __syncthreads();

        const uint32_t sb = sbase + (c & 1) * ST_BYTES;
#pragma unroll
        for (int ks = 0; ks < 4; ks++) {
            const uint32_t kb = ks * 32;
            uint32_t ah[2][4], al[2][4], bb[5][4];
            // hi A, hi B
#pragma unroll
            for (int mt = 0; mt < 2; mt++)
                ldsm4(ah[mt], sb + A_HI + aBase[mt] + ((kb + aKB) ^ aXor[mt]));
#pragma unroll
            for (int p = 0; p < 5; p++)
                ldsm4(bb[p], sb + B_HI + bBase[p] + ((kb + bKB) ^ bXor[p]));
            // pass 1: ah * bh
#pragma unroll
            for (int mt = 0; mt < 2; mt++)
#pragma unroll
                for (int p = 0; p < 5; p++) {
                    mma16816(acc[mt][p * 2 + 0], ah[mt], &bb[p][0]);
                    mma16816(acc[mt][p * 2 + 1], ah[mt], &bb[p][2]);
                }
            // lo A
#pragma unroll
            for (int mt = 0; mt < 2; mt++)
                ldsm4(al[mt], sb + A_LO + aBase[mt] + ((kb + aKB) ^ aXor[mt]));
            // pass 2: al * bh
#pragma unroll
            for (int mt = 0; mt < 2; mt++)
#pragma unroll
                for (int p = 0; p < 5; p++) {
                    mma16816(acc[mt][p * 2 + 0], al[mt], &bb[p][0]);
                    mma16816(acc[mt][p * 2 + 1], al[mt], &bb[p][2]);
                }
            // lo B (overwrite bb)
#pragma unroll
            for (int p = 0; p < 5; p++)
                ldsm4(bb[p], sb + B_LO + bBase[p] + ((kb + bKB) ^ bXor[p]));
            // pass 3: ah * bl
#pragma unroll
            for (int mt = 0; mt < 2; mt++)
#pragma unroll
                for (int p = 0; p < 5; p++) {
                    mma16816(acc[mt][p * 2 + 0], ah[mt], &bb[p][0]);
                    mma16816(acc[mt][p * 2 + 1], ah[mt], &bb[p][2]);
                }
        }
        __syncthreads();
    }

    // ---------------- epilogue ----------------
    float* s_log = reinterpret_cast<float*>(smem);   // [128][72]

#pragma unroll
    for (int mt = 0; mt < 2; mt++) {
        float u0 = 0.0f, u1 = 0.0f;
        const int row0 = wm * 32 + mt * 16 + (lane >> 2);
#pragma unroll
        for (int nt = 0; nt < 10; nt++) {
            const int nb = wn * 80 + nt * 8 + (lane & 3) * 2;
            const bool is_logit = (wn == 0 && nt < 8);
#pragma unroll
            for (int r = 0; r < 4; r++) {
                const int n = nb + (r & 1);
                const float v = acc[mt][nt][r];
                if (is_logit) {
                    const int rl = row0 + ((r >= 2) ? 8 : 0);
                    s_log[rl * 72 + n] = v;
                } else {
                    const int h = n - 64;
                    const float hh = fmaxf(v + __ldg(B1 + h), 0.0f) * __ldg(W2 + h);
                    if (r < 2) u0 += hh; else u1 += hh;
                }
            }
        }
        // reduce over the quad (lanes sharing the same rows)
        u0 += __shfl_xor_sync(0xffffffffu, u0, 1);
        u0 += __shfl_xor_sync(0xffffffffu, u0, 2);
        u1 += __shfl_xor_sync(0xffffffffu, u1, 1);
        u1 += __shfl_xor_sync(0xffffffffu, u1, 2);
        if ((lane & 3) == 0) {
            atomicAdd(&g_u[m0 + row0], u0);
            atomicAdd(&g_u[m0 + row0 + 8], u1);
        }
    }
    __syncthreads();

    // coalesced logits store: 128 rows x 64 floats
    for (int t = tid; t < MT * 16; t += THREADS) {
        int row = t >> 4, c4 = t & 15;
        float4 v = *reinterpret_cast<const float4*>(s_log + row * 72 + c4 * 4);
        *reinterpret_cast<float4*>(logits + (size_t)(m0 + row) * NEXP + c4 * 4) = v;
    }
}

// ---------------- per-token top-k / softmax / stats ----------------
#define CTOK 128
__global__ void __launch_bounds__(CTOK)
topk_kernel(const float* __restrict__ logits,
            float* __restrict__ sel,
            float* __restrict__ wts)
{
    __shared__ float sl[CTOK][NEXP + 1];
    __shared__ float sload[NEXP];
    __shared__ float s_ent;

    const int tid = threadIdx.x;
    const int t0 = blockIdx.x * CTOK;

    if (tid < NEXP) sload[tid] = 0.0f;
    if (tid == 0) s_ent = 0.0f;

    const float* src = logits + (size_t)t0 * NEXP;
    for (int idx = tid; idx < CTOK * NEXP; idx += CTOK) {
        sl[idx >> 6][idx & 63] = src[idx];
    }
    __syncthreads();

    const int m = t0 + tid;

    float v0 = -INFINITY, v1 = -INFINITY, v2 = -INFINITY, v3 = -INFINITY;
    int i0 = 0, i1 = 0, i2 = 0, i3 = 0;
#pragma unroll
    for (int j = 0; j < NEXP; j++) {
        float x = sl[tid][j];
        if (x > v3) {
            if (x > v0)      { v3=v2;i3=i2; v2=v1;i2=i1; v1=v0;i1=i0; v0=x;i0=j; }
            else if (x > v1) { v3=v2;i3=i2; v2=v1;i2=i1; v1=x;i1=j; }
            else if (x > v2) { v3=v2;i3=i2; v2=x;i2=j; }
            else             { v3=x;i3=j; }
        }
    }

    float se = 0.0f;
#pragma unroll
    for (int j = 0; j < NEXP; j++) {
        float e = __expf(sl[tid][j] - v0);
        se += e;
        sl[tid][j] = e;
    }
    float inv = 1.0f / se;

    float ent = 0.0f;
#pragma unroll
    for (int jj = 0; jj < NEXP; jj++) {
        int e = (jj + tid) & 63;
        float p = sl[tid][e] * inv;
        ent -= p * __logf(p + 1e-8f);
        atomicAdd(&sload[e], p);
    }
    atomicAdd(&s_ent, ent);

    float u = g_u[m];
    float cplx = 1.0f / (1.0f + expf(-u));
    int kk = (cplx > 0.5f) ? 4 : 1;

    float e0 = 1.0f;
    float e1 = (kk > 1) ? expf(v1 - v0) : 0.0f;
    float e2 = (kk > 2) ? expf(v2 - v0) : 0.0f;
    float e3 = (kk > 3) ? expf(v3 - v0) : 0.0f;
    float wi = 1.0f / (e0 + e1 + e2 + e3);

    float* selp = sel + (size_t)m * 4;
    float* wtp  = wts + (size_t)m * 4;
    selp[0] = (float)i0;
    selp[1] = (float)((kk > 1) ? i1 : 0);
    selp[2] = (float)((kk > 2) ? i2 : 0);
    selp[3] = (float)((kk > 3) ? i3 : 0);
    wtp[0] = e0 * wi;
    wtp[1] = e1 * wi;
    wtp[2] = e2 * wi;
    wtp[3] = e3 * wi;

    __syncthreads();
    if (tid < NEXP) atomicAdd(&g_load[tid], sload[tid]);
    if (tid == 0)   atomicAdd(&g_ent, s_ent);
}

// ---------------- finalize ----------------
__global__ void finalize_kernel(float* __restrict__ out_var, float* __restrict__ out_ent) {
    if (threadIdx.x == 0) {
        float xs[NEXP];
        float mean = 0.0f;
        for (int e = 0; e < NEXP; e++) { xs[e] = g_load[e] * (1.0f / N_TOK); mean += xs[e]; }
        mean *= (1.0f / NEXP);
        float var = 0.0f;
        for (int e = 0; e < NEXP; e++) { float d = xs[e] - mean; var += d * d; }
        out_var[0] = var * (1.0f / (NEXP - 1));
        out_ent[0] = g_ent * (1.0f / N_TOK);
    }
}

// ---------------- launch ----------------
extern "C" void kernel_launch(void* const* d_in, const int* in_sizes, int n_in,
                              void* d_out, int out_size) {
    const float* X  = (const float*)d_in[0];
    const float* RW = (const float*)d_in[1];
    const float* W1 = (const float*)d_in[2];
    const float* B1 = (const float*)d_in[3];
    const float* W2 = (const float*)d_in[4];
    const float* B2 = (const float*)d_in[5];

    float* out    = (float*)d_out;
    float* logits = out;
    float* sel    = logits + (size_t)N_TOK * NEXP;
    float* wts    = sel + (size_t)N_TOK * 4;
    float* ovar   = wts + (size_t)N_TOK * 4;
    float* oent   = ovar + 1;

    cudaFuncSetAttribute(gemm_kernel, cudaFuncAttributeMaxDynamicSharedMemorySize, SMEM_TOTAL);

    prep_w_kernel<<<(N_TOT * HID + 255) / 256, 256>>>(RW, W1);
    prep_x_kernel<<<(N_TOK * HID / 8) / 256, 256>>>(X);
    init_kernel<<<N_TOK / 256, 256>>>(B2);
    gemm_kernel<<<N_TOK / MT, THREADS, SMEM_TOTAL>>>(B1, W2, logits);
    topk_kernel<<<N_TOK / CTOK, CTOK>>>(logits, sel, wts);
    finalize_kernel<<<1, 64>>>(ovar, oent);
}